// round 16
// baseline (speedup 1.0000x reference)
#include <cuda_runtime.h>
#include <cuda_fp16.h>
#include <math.h>

#define NN 100000
#define NE 3200000
#define IND 128
#define HID 64
#define NG 256
#define NB 391          // ceil(NN/256) scan blocks

// ---------------- scratch (static device globals; no allocation) ----------------
__device__ int                g_is64;        // 1 if ei/batch int64, 0 if int32
__device__ unsigned long long g_packed[NN];  // [44:64) count, [0:44) fx weighted degree (ew * 2^20)
__device__ float              g_dis[NN];
__device__ int                g_cnt_node[NN];
__device__ int                g_bsum[NB];
__device__ int                g_offs[NN + 1];
__device__ int                g_offs_work[NN];
__device__ int2               g_csr[NE];      // packed {src row, norm bits}
__device__ uint4              g_xlh[NN * (HID / 8)];  // fp16 xl rows: 8 halves per uint4
__device__ float4             g_h4[NN * (HID / 4)];   // fp32 hidden state (layer 1)
__device__ float4             g_pool4[NG * (HID / 4)];
__device__ float              g_gcnt[NG];

// Explicit global-space vector reduction (16B-aligned dst).
__device__ __forceinline__ void red_add_v4(float4* dst, float4 v) {
    unsigned long long gaddr =
        (unsigned long long)__cvta_generic_to_global((void*)dst);
    asm volatile("red.global.add.v4.f32 [%0], {%1,%2,%3,%4};"
                 :: "l"(gaddr), "f"(v.x), "f"(v.y), "f"(v.z), "f"(v.w)
                 : "memory");
}

// Index load honoring detected dtype.
__device__ __forceinline__ int load_idx(const void* p, long long i) {
    if (g_is64) return (int)((const long long*)p)[i];
    return ((const int*)p)[i];
}

// ---------------- init + dtype detection ----------------
__global__ void k_init(const int* __restrict__ ei_words) {
    int i = blockIdx.x * blockDim.x + threadIdx.x;
    if (i < NN) g_packed[i] = 0ULL;
    if (blockIdx.x == 0 && threadIdx.x == 0) {
        int is64 = 1;
        for (int k = 0; k < 128; k++)
            if (ei_words[2 * k + 1] != 0) { is64 = 0; break; }
        g_is64 = is64;
    }
}

// ---------------- histogram + weighted degree: ONE packed atomic per edge ----
__global__ void k_hist(const void* __restrict__ ei, const float* __restrict__ ew) {
    int e = blockIdx.x * blockDim.x + threadIdx.x;
    if (e < NE) {
        int c = load_idx(ei, (long long)NE + e);
        if ((unsigned)c >= NN) c = 0;
        unsigned int fx = __float2uint_rn(ew[e] * 1048576.0f);  // ew * 2^20
        atomicAdd(&g_packed[c], (1ULL << 44) | (unsigned long long)fx);
    }
}

// ---------------- parallel exclusive scan over 100K counts ----------------
__global__ void __launch_bounds__(256) k_scan_partial() {
    __shared__ int s[256];
    int tid = threadIdx.x;
    int idx = blockIdx.x * 256 + tid;
    int v = 0;
    if (idx < NN) {
        unsigned long long p = g_packed[idx];
        v = (int)(p >> 44);
        float deg = (float)(p & 0xFFFFFFFFFFFULL) * (1.0f / 1048576.0f) + 1.0f;
        g_dis[idx] = rsqrtf(deg);   // deg >= 1 (self-loop weight 1)
        g_cnt_node[idx] = v;
    }
    s[tid] = v;
    __syncthreads();
#pragma unroll
    for (int o = 128; o > 0; o >>= 1) {
        if (tid < o) s[tid] += s[tid + o];
        __syncthreads();
    }
    if (tid == 0) g_bsum[blockIdx.x] = s[0];
}

__global__ void __launch_bounds__(512) k_scan_blocks() {
    __shared__ int s[512];
    int tid = threadIdx.x;
    int v = (tid < NB) ? g_bsum[tid] : 0;
    s[tid] = v;
    __syncthreads();
    for (int d = 1; d < 512; d <<= 1) {
        int t = (tid >= d) ? s[tid - d] : 0;
        __syncthreads();
        s[tid] += t;
        __syncthreads();
    }
    if (tid < NB) g_bsum[tid] = s[tid] - v;   // exclusive
    if (tid == 0) g_offs[NN] = NE;
}

__global__ void __launch_bounds__(256) k_scan_offs() {
    __shared__ int s[256];
    int tid = threadIdx.x;
    int idx = blockIdx.x * 256 + tid;
    int v = (idx < NN) ? g_cnt_node[idx] : 0;
    s[tid] = v;
    __syncthreads();
    for (int d = 1; d < 256; d <<= 1) {
        int t = (tid >= d) ? s[tid - d] : 0;
        __syncthreads();
        s[tid] += t;
        __syncthreads();
    }
    if (idx < NN) {
        int o = g_bsum[blockIdx.x] + s[tid] - v;
        g_offs[idx] = o;
        g_offs_work[idx] = o;
    }
}

// ---------------- permute edges into packed CSR (norm fused) ----------------
__global__ void k_permute(const void* __restrict__ ei, const float* __restrict__ ew) {
    int e = blockIdx.x * blockDim.x + threadIdx.x;
    if (e < NE) {
        int r = load_idx(ei, e);
        int c = load_idx(ei, (long long)NE + e);
        if ((unsigned)r >= NN) r = 0;
        if ((unsigned)c >= NN) c = 0;
        int slot = atomicAdd(&g_offs_work[c], 1);
        float w = g_dis[r] * ew[e] * g_dis[c];
        g_csr[slot] = make_int2(r, __float_as_int(w));
    }
}

// ---------------- tiled GEMM: xl = A[N,K] @ W[K,64], fp16 output ONLY --------
// SRC=0: A = Ain (harness input x). SRC=1: A = g_h4 (bound in device code --
// passing __device__ symbols as host args silently hits the host shadow via
// ATS on GB300). Accumulation fp32; single fp16 store (12.8MB total).
template <int K, int SRC>
__global__ void __launch_bounds__(128) k_mm(const float* __restrict__ Ain,
                                            const float* __restrict__ W) {
    constexpr int SP = K + 4;   // float4-aligned row stride
    constexpr int K4 = K / 4;
    __shared__ float As[64 * SP];
    const float* A = (SRC == 0) ? Ain : (const float*)g_h4;

    int tid = threadIdx.x;
    int row0 = blockIdx.x * 64;
    int rows_in = NN - row0; if (rows_in > 64) rows_in = 64;

    const float4* A4 = (const float4*)A;
    for (int f = tid; f < 64 * K4; f += 128) {
        int r = f / K4, kq = f % K4;
        float4 v = (r < rows_in) ? A4[(row0 + r) * K4 + kq]
                                 : make_float4(0.f, 0.f, 0.f, 0.f);
        *(float4*)&As[r * SP + kq * 4] = v;
    }
    __syncthreads();

    int ty = tid >> 4;
    int tx = tid & 15;
    const float4* W4 = (const float4*)W;
    float4 acc[8];
#pragma unroll
    for (int i = 0; i < 8; i++) acc[i] = make_float4(0.f, 0.f, 0.f, 0.f);

#pragma unroll 2
    for (int kq = 0; kq < K4; kq++) {
        float4 b0 = __ldg(&W4[(4 * kq + 0) * 16 + tx]);
        float4 b1 = __ldg(&W4[(4 * kq + 1) * 16 + tx]);
        float4 b2 = __ldg(&W4[(4 * kq + 2) * 16 + tx]);
        float4 b3 = __ldg(&W4[(4 * kq + 3) * 16 + tx]);
#pragma unroll
        for (int i = 0; i < 8; i++) {
            float4 a = *(const float4*)&As[(ty + 8 * i) * SP + 4 * kq];
            acc[i].x = fmaf(a.x, b0.x, acc[i].x);
            acc[i].y = fmaf(a.x, b0.y, acc[i].y);
            acc[i].z = fmaf(a.x, b0.z, acc[i].z);
            acc[i].w = fmaf(a.x, b0.w, acc[i].w);
            acc[i].x = fmaf(a.y, b1.x, acc[i].x);
            acc[i].y = fmaf(a.y, b1.y, acc[i].y);
            acc[i].z = fmaf(a.y, b1.z, acc[i].z);
            acc[i].w = fmaf(a.y, b1.w, acc[i].w);
            acc[i].x = fmaf(a.z, b2.x, acc[i].x);
            acc[i].y = fmaf(a.z, b2.y, acc[i].y);
            acc[i].z = fmaf(a.z, b2.z, acc[i].z);
            acc[i].w = fmaf(a.z, b2.w, acc[i].w);
            acc[i].x = fmaf(a.w, b3.x, acc[i].x);
            acc[i].y = fmaf(a.w, b3.y, acc[i].y);
            acc[i].z = fmaf(a.w, b3.z, acc[i].z);
            acc[i].w = fmaf(a.w, b3.w, acc[i].w);
        }
    }
#pragma unroll
    for (int i = 0; i < 8; i++) {
        int r = ty + 8 * i;
        if (r < rows_in) {
            __half2 lo = __floats2half2_rn(acc[i].x, acc[i].y);
            __half2 hi = __floats2half2_rn(acc[i].z, acc[i].w);
            ((uint2*)g_xlh)[(row0 + r) * 16 + tx] =
                make_uint2(*(unsigned*)&lo, *(unsigned*)&hi);
        }
    }
}

// ---------------- warp-per-node CSR aggregation, 4 edges in flight -----------
// 8 lanes/edge (one uint4 = 8 fp16 features each), 4 edges concurrently.
// h[n] = relu( sum_e w_e * xl16[src_e] + dis[n]^2 * xl16[n] + b ), fp32 accum.
// FUSE_POOL=0: write to g_h4. FUSE_POOL=1: red into g_pool4[batch[n]] instead.
template <int FUSE_POOL>
__global__ void __launch_bounds__(256) k_agg(const float* __restrict__ bias,
                                             const void* __restrict__ batch) {
    int warp = (blockIdx.x * blockDim.x + threadIdx.x) >> 5;
    if (warp >= NN) return;
    int lane = threadIdx.x & 31;
    int q = lane & 7;       // 8-feature chunk (uint4) of the 64-wide feature
    int sub = lane >> 3;    // which of 4 edges in flight
    int n = warp;
    int start = g_offs[n], end = g_offs[n + 1];

    float a0 = 0.f, a1 = 0.f, a2 = 0.f, a3 = 0.f,
          a4 = 0.f, a5 = 0.f, a6 = 0.f, a7 = 0.f;
#pragma unroll 2
    for (int i = start + sub; i < end; i += 4) {
        int2 ed = g_csr[i];
        int r = ed.x;
        float w = __int_as_float(ed.y);
        uint4 hv = g_xlh[r * 8 + q];             // 8 halves = 16B
        float2 f0 = __half22float2(*(__half2*)&hv.x);
        float2 f1 = __half22float2(*(__half2*)&hv.y);
        float2 f2 = __half22float2(*(__half2*)&hv.z);
        float2 f3 = __half22float2(*(__half2*)&hv.w);
        a0 = fmaf(w, f0.x, a0); a1 = fmaf(w, f0.y, a1);
        a2 = fmaf(w, f1.x, a2); a3 = fmaf(w, f1.y, a3);
        a4 = fmaf(w, f2.x, a4); a5 = fmaf(w, f2.y, a5);
        a6 = fmaf(w, f3.x, a6); a7 = fmaf(w, f3.y, a7);
    }
    // reduce across the 4 edge-slots (lanes differing in bits 3,4)
#pragma unroll
    for (int o = 8; o <= 16; o <<= 1) {
        a0 += __shfl_xor_sync(0xffffffff, a0, o);
        a1 += __shfl_xor_sync(0xffffffff, a1, o);
        a2 += __shfl_xor_sync(0xffffffff, a2, o);
        a3 += __shfl_xor_sync(0xffffffff, a3, o);
        a4 += __shfl_xor_sync(0xffffffff, a4, o);
        a5 += __shfl_xor_sync(0xffffffff, a5, o);
        a6 += __shfl_xor_sync(0xffffffff, a6, o);
        a7 += __shfl_xor_sync(0xffffffff, a7, o);
    }

    if (sub == 0) {                              // lanes 0..7
        float d = g_dis[n];
        float d2 = d * d;
        uint4 sh = g_xlh[n * 8 + q];             // self term (fp16)
        float2 s0 = __half22float2(*(__half2*)&sh.x);
        float2 s1 = __half22float2(*(__half2*)&sh.y);
        float2 s2 = __half22float2(*(__half2*)&sh.z);
        float2 s3 = __half22float2(*(__half2*)&sh.w);
        const float4* b4 = (const float4*)bias;
        float4 bA = b4[2 * q], bB = b4[2 * q + 1];
        float4 resA, resB;
        resA.x = fmaxf(fmaf(d2, s0.x, a0) + bA.x, 0.f);
        resA.y = fmaxf(fmaf(d2, s0.y, a1) + bA.y, 0.f);
        resA.z = fmaxf(fmaf(d2, s1.x, a2) + bA.z, 0.f);
        resA.w = fmaxf(fmaf(d2, s1.y, a3) + bA.w, 0.f);
        resB.x = fmaxf(fmaf(d2, s2.x, a4) + bB.x, 0.f);
        resB.y = fmaxf(fmaf(d2, s2.y, a5) + bB.y, 0.f);
        resB.z = fmaxf(fmaf(d2, s3.x, a6) + bB.z, 0.f);
        resB.w = fmaxf(fmaf(d2, s3.y, a7) + bB.w, 0.f);
        if (FUSE_POOL) {
            int g = load_idx(batch, n);
            if ((unsigned)g >= NG) g = 0;
            red_add_v4(&g_pool4[g * 16 + 2 * q], resA);
            red_add_v4(&g_pool4[g * 16 + 2 * q + 1], resB);
            if (lane == 0) atomicAdd(&g_gcnt[g], 1.0f);
        } else {
            g_h4[n * 16 + 2 * q] = resA;
            g_h4[n * 16 + 2 * q + 1] = resB;
        }
    }
}

// ---------------- zero pool ----------------
__global__ void k_zero_pool() {
    int t = blockIdx.x * blockDim.x + threadIdx.x;
    if (t < NG * (HID / 4))
        g_pool4[t] = make_float4(0.f, 0.f, 0.f, 0.f);
    if (t < NG) g_gcnt[t] = 0.f;
}

// ---------------- classifier head ----------------
__global__ void k_final(const float* __restrict__ Wc, const float* __restrict__ bc,
                        float* __restrict__ out) {
    int g = blockIdx.x;
    int j = threadIdx.x;
    __shared__ float s[HID];
    const float* pool = (const float*)g_pool4;
    float c = fmaxf(g_gcnt[g], 1.0f);
    s[j] = pool[g * HID + j] / c * Wc[j];
    __syncthreads();
#pragma unroll
    for (int o = 32; o > 0; o >>= 1) {
        if (j < o) s[j] += s[j + o];
        __syncthreads();
    }
    if (j == 0) out[g] = s[0] + bc[0];
}

// ---------------- launch ----------------
extern "C" void kernel_launch(void* const* d_in, const int* in_sizes, int n_in,
                              void* d_out, int out_size) {
    const float* x     = (const float*)d_in[0];
    const void*  ei    = d_in[1];
    const float* ew    = (const float*)d_in[2];
    const void*  batch = d_in[3];
    const float* W1    = (const float*)d_in[4];
    const float* b1    = (const float*)d_in[5];
    const float* W2    = (const float*)d_in[6];
    const float* b2    = (const float*)d_in[7];
    const float* Wc    = (const float*)d_in[8];
    const float* bc    = (const float*)d_in[9];
    float*       out   = (float*)d_out;

    // Lazily-created side stream + events (objects cached; identical launch
    // pattern every call -> deterministic, graph-capturable fork/join).
    static cudaStream_t s_side = nullptr;
    static cudaEvent_t  ev_fork = nullptr, ev_join = nullptr;
    if (s_side == nullptr) {
        cudaStreamCreateWithFlags(&s_side, cudaStreamNonBlocking);
        cudaEventCreateWithFlags(&ev_fork, cudaEventDisableTiming);
        cudaEventCreateWithFlags(&ev_join, cudaEventDisableTiming);
    }

    const int T = 256;

    // ---- fork: mm1 (x@W1) + pool zeroing run parallel to the CSR build ----
    cudaEventRecord(ev_fork, 0);
    cudaStreamWaitEvent(s_side, ev_fork, 0);
    k_mm<IND, 0><<<(NN + 63) / 64, 128, 0, s_side>>>(x, W1);
    k_zero_pool<<<(NG * HID + T - 1) / T, T, 0, s_side>>>();
    cudaEventRecord(ev_join, s_side);

    // ---- main stream: CSR + normalization precompute ----
    k_init<<<(NN + T - 1) / T, T>>>((const int*)ei);
    k_hist<<<(NE + T - 1) / T, T>>>(ei, ew);
    k_scan_partial<<<NB, 256>>>();
    k_scan_blocks<<<1, 512>>>();
    k_scan_offs<<<NB, 256>>>();
    k_permute<<<(NE + T - 1) / T, T>>>(ei, ew);

    // ---- join, then the dependent chain ----
    cudaStreamWaitEvent(0, ev_join, 0);
    k_agg<0><<<(NN * 32 + T - 1) / T, T>>>(b1, batch);
    k_mm<HID, 1><<<(NN + 63) / 64, 128>>>(nullptr, W2);
    k_agg<1><<<(NN * 32 + T - 1) / T, T>>>(b2, batch);
    k_final<<<NG, HID>>>(Wc, bc, out);
}

// round 17
// speedup vs baseline: 1.0348x; 1.0348x over previous
#include <cuda_runtime.h>
#include <cuda_fp16.h>
#include <math.h>

#define NN 100000
#define NE 3200000
#define IND 128
#define HID 64
#define NG 256
#define NB 391          // ceil(NN/256) scan blocks

// ---------------- scratch (static device globals; no allocation) ----------------
__device__ int                g_is64;        // 1 if ei/batch int64, 0 if int32
__device__ unsigned long long g_packed[NN];  // [44:64) count, [0:44) fx weighted degree (ew * 2^20)
__device__ float              g_dis[NN];
__device__ int                g_cnt_node[NN];
__device__ int                g_bsum[NB];
__device__ int                g_offs[NN + 1];
__device__ int                g_offs_work[NN];
__device__ unsigned           g_csrp[NE];     // [17:32) u=ew*dis[r] fx15, [0:17) src row
__device__ uint2              g_xlh[NN * (HID / 4)];  // fp16 xl: 4 halves per uint2
__device__ uint2              g_hh[NN * (HID / 4)];   // fp16 hidden state (layer 1)
__device__ float4             g_pool4[NG * (HID / 4)];
__device__ float              g_gcnt[NG];

// Explicit global-space vector reduction (16B-aligned dst).
__device__ __forceinline__ void red_add_v4(float4* dst, float4 v) {
    unsigned long long gaddr =
        (unsigned long long)__cvta_generic_to_global((void*)dst);
    asm volatile("red.global.add.v4.f32 [%0], {%1,%2,%3,%4};"
                 :: "l"(gaddr), "f"(v.x), "f"(v.y), "f"(v.z), "f"(v.w)
                 : "memory");
}

// Index load honoring detected dtype.
__device__ __forceinline__ int load_idx(const void* p, long long i) {
    if (g_is64) return (int)((const long long*)p)[i];
    return ((const int*)p)[i];
}

// ---------------- init + dtype detection ----------------
__global__ void k_init(const int* __restrict__ ei_words) {
    int i = blockIdx.x * blockDim.x + threadIdx.x;
    if (i < NN) g_packed[i] = 0ULL;
    if (blockIdx.x == 0 && threadIdx.x == 0) {
        int is64 = 1;
        for (int k = 0; k < 128; k++)
            if (ei_words[2 * k + 1] != 0) { is64 = 0; break; }
        g_is64 = is64;
    }
}

// ---------------- histogram + weighted degree: ONE packed atomic per edge ----
__global__ void k_hist(const void* __restrict__ ei, const float* __restrict__ ew) {
    int e = blockIdx.x * blockDim.x + threadIdx.x;
    if (e < NE) {
        int c = load_idx(ei, (long long)NE + e);
        if ((unsigned)c >= NN) c = 0;
        unsigned int fx = __float2uint_rn(ew[e] * 1048576.0f);  // ew * 2^20
        atomicAdd(&g_packed[c], (1ULL << 44) | (unsigned long long)fx);
    }
}

// ---------------- scan stage 1: unpack counts, dis; per-block sums ----------
__global__ void __launch_bounds__(256) k_scan_partial() {
    __shared__ int s[256];
    int tid = threadIdx.x;
    int idx = blockIdx.x * 256 + tid;
    int v = 0;
    if (idx < NN) {
        unsigned long long p = g_packed[idx];
        v = (int)(p >> 44);
        float deg = (float)(p & 0xFFFFFFFFFFFULL) * (1.0f / 1048576.0f) + 1.0f;
        g_dis[idx] = rsqrtf(deg);   // deg >= 1 (self-loop weight 1)
        g_cnt_node[idx] = v;
    }
    s[tid] = v;
    __syncthreads();
#pragma unroll
    for (int o = 128; o > 0; o >>= 1) {
        if (tid < o) s[tid] += s[tid + o];
        __syncthreads();
    }
    if (tid == 0) g_bsum[blockIdx.x] = s[0];
}

// ---------------- scan stage 2 (merged): block base + local scan -> offs ----
__global__ void __launch_bounds__(256) k_scan_offs() {
    __shared__ int rs[256];
    __shared__ int s[256];
    int tid = threadIdx.x;
    int idx = blockIdx.x * 256 + tid;

    // base = sum of bsum[0 .. blockIdx.x)
    int b = 0;
    for (int t = tid; t < blockIdx.x; t += 256) b += g_bsum[t];
    rs[tid] = b;
    __syncthreads();
#pragma unroll
    for (int o = 128; o > 0; o >>= 1) {
        if (tid < o) rs[tid] += rs[tid + o];
        __syncthreads();
    }
    int base = rs[0];

    int v = (idx < NN) ? g_cnt_node[idx] : 0;
    s[tid] = v;
    __syncthreads();
    for (int d = 1; d < 256; d <<= 1) {
        int t = (tid >= d) ? s[tid - d] : 0;
        __syncthreads();
        s[tid] += t;
        __syncthreads();
    }
    if (idx < NN) {
        int o = base + s[tid] - v;
        g_offs[idx] = o;
        g_offs_work[idx] = o;
    }
    if (blockIdx.x == 0 && tid == 0) g_offs[NN] = NE;
}

// ---------------- permute edges into 4B packed CSR ---------------------------
// entry = (fx15(ew*dis[r]) << 17) | r  ; dis[c] is factored into the agg epilogue.
__global__ void k_permute(const void* __restrict__ ei, const float* __restrict__ ew) {
    int e = blockIdx.x * blockDim.x + threadIdx.x;
    if (e < NE) {
        int r = load_idx(ei, e);
        int c = load_idx(ei, (long long)NE + e);
        if ((unsigned)r >= NN) r = 0;
        if ((unsigned)c >= NN) c = 0;
        int slot = atomicAdd(&g_offs_work[c], 1);
        float u = ew[e] * g_dis[r];                       // in [0,1)
        unsigned fx = __float2uint_rn(u * 32768.0f);
        if (fx > 32767u) fx = 32767u;
        g_csrp[slot] = (fx << 17) | (unsigned)r;
    }
}

// ---------------- tiled GEMM: xl = A[N,K] @ W[K,64], fp16 in (SRC=1) / out ---
// SRC=0: A = Ain (harness input x, fp32). SRC=1: A = g_hh (fp16, bound in
// device code -- passing __device__ symbols as host args silently hits the
// host shadow via ATS on GB300). Accumulation fp32; fp16 store.
template <int K, int SRC>
__global__ void __launch_bounds__(128) k_mm(const float* __restrict__ Ain,
                                            const float* __restrict__ W) {
    constexpr int SP = K + 4;   // float4-aligned row stride
    constexpr int K4 = K / 4;
    __shared__ float As[64 * SP];

    int tid = threadIdx.x;
    int row0 = blockIdx.x * 64;
    int rows_in = NN - row0; if (rows_in > 64) rows_in = 64;

    for (int f = tid; f < 64 * K4; f += 128) {
        int r = f / K4, kq = f % K4;
        float4 v = make_float4(0.f, 0.f, 0.f, 0.f);
        if (r < rows_in) {
            if (SRC == 0) {
                v = ((const float4*)Ain)[(row0 + r) * K4 + kq];
            } else {
                uint2 hv = g_hh[(row0 + r) * K4 + kq];
                float2 lo = __half22float2(*(__half2*)&hv.x);
                float2 hi = __half22float2(*(__half2*)&hv.y);
                v = make_float4(lo.x, lo.y, hi.x, hi.y);
            }
        }
        *(float4*)&As[r * SP + kq * 4] = v;
    }
    __syncthreads();

    int ty = tid >> 4;
    int tx = tid & 15;
    const float4* W4 = (const float4*)W;
    float4 acc[8];
#pragma unroll
    for (int i = 0; i < 8; i++) acc[i] = make_float4(0.f, 0.f, 0.f, 0.f);

#pragma unroll 2
    for (int kq = 0; kq < K4; kq++) {
        float4 b0 = __ldg(&W4[(4 * kq + 0) * 16 + tx]);
        float4 b1 = __ldg(&W4[(4 * kq + 1) * 16 + tx]);
        float4 b2 = __ldg(&W4[(4 * kq + 2) * 16 + tx]);
        float4 b3 = __ldg(&W4[(4 * kq + 3) * 16 + tx]);
#pragma unroll
        for (int i = 0; i < 8; i++) {
            float4 a = *(const float4*)&As[(ty + 8 * i) * SP + 4 * kq];
            acc[i].x = fmaf(a.x, b0.x, acc[i].x);
            acc[i].y = fmaf(a.x, b0.y, acc[i].y);
            acc[i].z = fmaf(a.x, b0.z, acc[i].z);
            acc[i].w = fmaf(a.x, b0.w, acc[i].w);
            acc[i].x = fmaf(a.y, b1.x, acc[i].x);
            acc[i].y = fmaf(a.y, b1.y, acc[i].y);
            acc[i].z = fmaf(a.y, b1.z, acc[i].z);
            acc[i].w = fmaf(a.y, b1.w, acc[i].w);
            acc[i].x = fmaf(a.z, b2.x, acc[i].x);
            acc[i].y = fmaf(a.z, b2.y, acc[i].y);
            acc[i].z = fmaf(a.z, b2.z, acc[i].z);
            acc[i].w = fmaf(a.z, b2.w, acc[i].w);
            acc[i].x = fmaf(a.w, b3.x, acc[i].x);
            acc[i].y = fmaf(a.w, b3.y, acc[i].y);
            acc[i].z = fmaf(a.w, b3.z, acc[i].z);
            acc[i].w = fmaf(a.w, b3.w, acc[i].w);
        }
    }
#pragma unroll
    for (int i = 0; i < 8; i++) {
        int r = ty + 8 * i;
        if (r < rows_in) {
            __half2 lo = __floats2half2_rn(acc[i].x, acc[i].y);
            __half2 hi = __floats2half2_rn(acc[i].z, acc[i].w);
            g_xlh[(row0 + r) * 16 + tx] =
                make_uint2(*(unsigned*)&lo, *(unsigned*)&hi);
        }
    }
}

// ---------------- warp-per-node CSR aggregation, fused epilogue --------------
// h[n] = relu( dis[n] * sum_e u_e*xl16[src_e] + dis[n]^2*xl16[n] + b ), fp32 accum.
// FUSE_POOL=0: write fp16 h to g_hh. FUSE_POOL=1: red into g_pool4[batch[n]].
template <int FUSE_POOL>
__global__ void __launch_bounds__(256) k_agg(const float* __restrict__ bias,
                                             const void* __restrict__ batch) {
    int warp = (blockIdx.x * blockDim.x + threadIdx.x) >> 5;
    if (warp >= NN) return;
    int lane = threadIdx.x & 31;
    int q = lane & 15;      // 4-feature chunk (uint2) of the 64-wide feature
    int sub = lane >> 4;    // which of 2 edges in flight
    int n = warp;
    int start = g_offs[n], end = g_offs[n + 1];

    float4 acc = make_float4(0.f, 0.f, 0.f, 0.f);
#pragma unroll 4
    for (int i = start + sub; i < end; i += 2) {
        unsigned p = g_csrp[i];
        int r = (int)(p & 0x1FFFFu);
        float u = (float)(p >> 17) * (1.0f / 32768.0f);
        uint2 hv = g_xlh[r * 16 + q];            // 4 halves = 8B
        float2 lo = __half22float2(*(__half2*)&hv.x);
        float2 hi = __half22float2(*(__half2*)&hv.y);
        acc.x = fmaf(u, lo.x, acc.x);
        acc.y = fmaf(u, lo.y, acc.y);
        acc.z = fmaf(u, hi.x, acc.z);
        acc.w = fmaf(u, hi.y, acc.w);
    }
    acc.x += __shfl_xor_sync(0xffffffff, acc.x, 16);
    acc.y += __shfl_xor_sync(0xffffffff, acc.y, 16);
    acc.z += __shfl_xor_sync(0xffffffff, acc.z, 16);
    acc.w += __shfl_xor_sync(0xffffffff, acc.w, 16);

    if (sub == 0) {
        float d = g_dis[n];
        float d2 = d * d;
        uint2 sh = g_xlh[n * 16 + q];            // self term (fp16)
        float2 slo = __half22float2(*(__half2*)&sh.x);
        float2 shi = __half22float2(*(__half2*)&sh.y);
        float4 b4 = ((const float4*)bias)[q];
        float4 res;
        res.x = fmaxf(fmaf(d, acc.x, fmaf(d2, slo.x, b4.x)), 0.f);
        res.y = fmaxf(fmaf(d, acc.y, fmaf(d2, slo.y, b4.y)), 0.f);
        res.z = fmaxf(fmaf(d, acc.z, fmaf(d2, shi.x, b4.z)), 0.f);
        res.w = fmaxf(fmaf(d, acc.w, fmaf(d2, shi.y, b4.w)), 0.f);
        if (FUSE_POOL) {
            int g = load_idx(batch, n);
            if ((unsigned)g >= NG) g = 0;
            red_add_v4(&g_pool4[g * 16 + q], res);
            if (lane == 0) atomicAdd(&g_gcnt[g], 1.0f);
        } else {
            __half2 lo = __floats2half2_rn(res.x, res.y);
            __half2 hi = __floats2half2_rn(res.z, res.w);
            g_hh[n * 16 + q] = make_uint2(*(unsigned*)&lo, *(unsigned*)&hi);
        }
    }
}

// ---------------- zero pool ----------------
__global__ void k_zero_pool() {
    int t = blockIdx.x * blockDim.x + threadIdx.x;
    if (t < NG * (HID / 4))
        g_pool4[t] = make_float4(0.f, 0.f, 0.f, 0.f);
    if (t < NG) g_gcnt[t] = 0.f;
}

// ---------------- classifier head ----------------
__global__ void k_final(const float* __restrict__ Wc, const float* __restrict__ bc,
                        float* __restrict__ out) {
    int g = blockIdx.x;
    int j = threadIdx.x;
    __shared__ float s[HID];
    const float* pool = (const float*)g_pool4;
    float c = fmaxf(g_gcnt[g], 1.0f);
    s[j] = pool[g * HID + j] / c * Wc[j];
    __syncthreads();
#pragma unroll
    for (int o = 32; o > 0; o >>= 1) {
        if (j < o) s[j] += s[j + o];
        __syncthreads();
    }
    if (j == 0) out[g] = s[0] + bc[0];
}

// ---------------- launch ----------------
extern "C" void kernel_launch(void* const* d_in, const int* in_sizes, int n_in,
                              void* d_out, int out_size) {
    const float* x     = (const float*)d_in[0];
    const void*  ei    = d_in[1];
    const float* ew    = (const float*)d_in[2];
    const void*  batch = d_in[3];
    const float* W1    = (const float*)d_in[4];
    const float* b1    = (const float*)d_in[5];
    const float* W2    = (const float*)d_in[6];
    const float* b2    = (const float*)d_in[7];
    const float* Wc    = (const float*)d_in[8];
    const float* bc    = (const float*)d_in[9];
    float*       out   = (float*)d_out;

    // Lazily-created side stream + events (objects cached; identical launch
    // pattern every call -> deterministic, graph-capturable fork/join).
    static cudaStream_t s_side = nullptr;
    static cudaEvent_t  ev_fork = nullptr, ev_join = nullptr;
    if (s_side == nullptr) {
        cudaStreamCreateWithFlags(&s_side, cudaStreamNonBlocking);
        cudaEventCreateWithFlags(&ev_fork, cudaEventDisableTiming);
        cudaEventCreateWithFlags(&ev_join, cudaEventDisableTiming);
    }

    const int T = 256;

    // ---- fork: mm1 (x@W1) + pool zeroing run parallel to the CSR build ----
    cudaEventRecord(ev_fork, 0);
    cudaStreamWaitEvent(s_side, ev_fork, 0);
    k_mm<IND, 0><<<(NN + 63) / 64, 128, 0, s_side>>>(x, W1);
    k_zero_pool<<<(NG * HID + T - 1) / T, T, 0, s_side>>>();
    cudaEventRecord(ev_join, s_side);

    // ---- main stream: CSR + normalization precompute ----
    k_init<<<(NN + T - 1) / T, T>>>((const int*)ei);
    k_hist<<<(NE + T - 1) / T, T>>>(ei, ew);
    k_scan_partial<<<NB, 256>>>();
    k_scan_offs<<<NB, 256>>>();
    k_permute<<<(NE + T - 1) / T, T>>>(ei, ew);

    // ---- join, then the dependent chain ----
    cudaStreamWaitEvent(0, ev_join, 0);
    k_agg<0><<<(NN * 32 + T - 1) / T, T>>>(b1, batch);
    k_mm<HID, 1><<<(NN + 63) / 64, 128>>>(nullptr, W2);
    k_agg<1><<<(NN * 32 + T - 1) / T, T>>>(b2, batch);
    k_final<<<NG, HID>>>(Wc, bc, out);
}